// round 14
// baseline (speedup 1.0000x reference)
#include <cuda_runtime.h>
#include <cuda_bf16.h>
#include <cstdio>

#define BB 2
#define HH 12
#define SS 2048
#define DH 64
#define DM 768
#define MM (BB * SS)                                   // 4096
#define ACT_ELEMS ((long long)BB * SS * DM)            // 3,145,728
#define QKV_ELEMS ((long long)BB * HH * SS * DH)       // 3,145,728
#define W_ELEMS ((long long)DM * DM)                   // 589,824
#define OUT_ELEMS ((long long)BB * SS * DM)            // 3,145,728
#define ATTN_ELEMS ((long long)BB * HH * SS * SS)      // 100,663,296

// Static device scratch.
__device__ __align__(16) float g_v[3145728];
__device__ __align__(16) __nv_bfloat16 g_qh[3145728];
__device__ __align__(16) __nv_bfloat16 g_ql[3145728];
__device__ __align__(16) __nv_bfloat16 g_kh[3145728];
__device__ __align__(16) __nv_bfloat16 g_kl[3145728];
__device__ __align__(16) __nv_bfloat16 g_ctxh[3145728];
__device__ __align__(16) __nv_bfloat16 g_ctxl[3145728];
// Pre-split activations (query|key|value) and weights (W_q|W_k|W_v|W_o).
__device__ __align__(16) __nv_bfloat16 g_axh[3 * 3145728];
__device__ __align__(16) __nv_bfloat16 g_axl[3 * 3145728];
__device__ __align__(16) __nv_bfloat16 g_wsh[4 * 589824];
__device__ __align__(16) __nv_bfloat16 g_wsl[4 * 589824];

// Guarded accessors (proven shell).
__device__ __forceinline__ float gld(const float* __restrict__ p, long long i, long long n) {
    return (i >= 0 && i < n) ? __ldg(p + i) : 0.f;
}
__device__ __forceinline__ void gst(float* __restrict__ p, long long i, long long n, float v) {
    if (i >= 0 && i < n) p[i] = v;
}
__device__ __forceinline__ void gst2(float* __restrict__ p, long long i, long long n, float a, float b) {
    if (i >= 0 && i + 1 < n) { float2 t = {a, b}; *(float2*)(p + i) = t; }
}
__device__ __forceinline__ float4 gld4(const float* __restrict__ p, long long i, long long n) {
    if (i >= 0 && i + 3 < n) return __ldg((const float4*)(p + i));
    float4 z = {0.f, 0.f, 0.f, 0.f};
    return z;
}
__device__ __forceinline__ void gstb(__nv_bfloat16* p, long long i, long long n, __nv_bfloat16 v) {
    if (i >= 0 && i < n) p[i] = v;
}
__device__ __forceinline__ uint2 gldb4(const __nv_bfloat16* __restrict__ p, long long i, long long n) {
    if (i >= 0 && i + 3 < n) return *(const uint2*)(p + i);
    return make_uint2(0u, 0u);
}
__device__ __forceinline__ void gstb4(__nv_bfloat16* p, long long i, long long n, uint2 v) {
    if (i >= 0 && i + 3 < n) *(uint2*)(p + i) = v;
}

// bf16 hi/lo split.
__device__ __forceinline__ void f2bf2(float x, __nv_bfloat16& h, __nv_bfloat16& l) {
    h = __float2bfloat16_rn(x);
    l = __float2bfloat16_rn(x - __bfloat162float(h));
}
__device__ __forceinline__ void split4(float4 x, uint2& h, uint2& l) {
    __nv_bfloat16 h0, l0, h1, l1, h2, l2, h3, l3;
    f2bf2(x.x, h0, l0); f2bf2(x.y, h1, l1);
    f2bf2(x.z, h2, l2); f2bf2(x.w, h3, l3);
    h.x = ((unsigned)__bfloat16_as_ushort(h1) << 16) | __bfloat16_as_ushort(h0);
    h.y = ((unsigned)__bfloat16_as_ushort(h3) << 16) | __bfloat16_as_ushort(h2);
    l.x = ((unsigned)__bfloat16_as_ushort(l1) << 16) | __bfloat16_as_ushort(l0);
    l.y = ((unsigned)__bfloat16_as_ushort(l3) << 16) | __bfloat16_as_ushort(l2);
}

#define MMA_BF16(d, a, b0v, b1v)                                                 \
    asm volatile(                                                                \
        "mma.sync.aligned.m16n8k16.row.col.f32.bf16.bf16.f32 "                   \
        "{%0,%1,%2,%3}, {%4,%5,%6,%7}, {%8,%9}, {%0,%1,%2,%3};"                  \
        : "+f"((d)[0]), "+f"((d)[1]), "+f"((d)[2]), "+f"((d)[3])                 \
        : "r"((a)[0]), "r"((a)[1]), "r"((a)[2]), "r"((a)[3]), "r"(b0v), "r"(b1v));

// ===========================================================================
// Pre-split: fp32 -> bf16 hi/lo for 3 activations + 4 weights.
// ===========================================================================
__global__ void __launch_bounds__(256) split_all_kernel(
    const float* __restrict__ q, const float* __restrict__ k,
    const float* __restrict__ v, const float* __restrict__ wq,
    const float* __restrict__ wk, const float* __restrict__ wv,
    const float* __restrict__ wo)
{
    const int t = blockIdx.y;
    const float* src = (t == 0) ? q : (t == 1) ? k : (t == 2) ? v
                     : (t == 3) ? wq : (t == 4) ? wk : (t == 5) ? wv : wo;
    const long long nelem = (t < 3) ? ACT_ELEMS : W_ELEMS;
    const long long nq = nelem >> 2;
    __nv_bfloat16* dh;
    __nv_bfloat16* dl;
    long long off;
    long long dn;
    if (t < 3) { dh = g_axh; dl = g_axl; off = (long long)t * ACT_ELEMS; dn = 3 * ACT_ELEMS; }
    else       { dh = g_wsh; dl = g_wsl; off = (long long)(t - 3) * W_ELEMS; dn = 4 * W_ELEMS; }

    for (long long i = (long long)blockIdx.x * 256 + threadIdx.x; i < nq;
         i += (long long)gridDim.x * 256) {
        float4 x = gld4(src, i * 4, nelem);
        uint2 h, l;
        split4(x, h, l);
        gstb4(dh, off + i * 4, dn, h);
        gstb4(dl, off + i * 4, dn, l);
    }
}

// ===========================================================================
// FUSED projection GEMM: blockIdx.z = 0(Q)/1(K)/2(V). Pre-split inputs,
// register double-buffer. Q epilogue pre-scales by 0.125 (exact pow2).
// Block 128m x 64n, 8 warps (32x32), BK=32. grid (12, 32, 3).
// ===========================================================================
__global__ void __launch_bounds__(256) proj_mma_kernel(
    const float* __restrict__ b_q, const float* __restrict__ b_k,
    const float* __restrict__ b_v)
{
    __shared__ __nv_bfloat16 Ah_s[128 * 40];
    __shared__ __nv_bfloat16 Al_s[128 * 40];
    __shared__ __nv_bfloat16 Wh_s[64 * 40];
    __shared__ __nv_bfloat16 Wl_s[64 * 40];

    const int z = blockIdx.z;
    const float* bias = (z == 0) ? b_q : (z == 1) ? b_k : b_v;

    const int tid = threadIdx.x;
    const int warp = tid >> 5, lane = tid & 31;
    const int warp_m = warp & 3, warp_n = warp >> 2;
    const int row0 = blockIdx.y * 128, col0 = blockIdx.x * 64;
    const int lr = lane >> 2, lc2 = (lane & 3) * 2;
    const long long aoff = (long long)z * ACT_ELEMS;
    const long long woff = (long long)z * W_ELEMS;

    uint2 pAh[4], pAl[4], pWh[2], pWl[2];

    auto fetch = [&](int k0) {
#pragma unroll
        for (int it = 0; it < 4; it++) {
            int v = tid + it * 256;
            int m = v >> 3, kq = (v & 7) * 4;
            long long ai = aoff + (long long)(row0 + m) * DM + k0 + kq;
            pAh[it] = gldb4(g_axh, ai, 3 * ACT_ELEMS);
            pAl[it] = gldb4(g_axl, ai, 3 * ACT_ELEMS);
        }
#pragma unroll
        for (int it = 0; it < 2; it++) {
            int v = tid + it * 256;
            int n = v >> 3, kq = (v & 7) * 4;
            long long wi = woff + (long long)(col0 + n) * DM + k0 + kq;
            pWh[it] = gldb4(g_wsh, wi, 4 * W_ELEMS);
            pWl[it] = gldb4(g_wsl, wi, 4 * W_ELEMS);
        }
    };
    auto store_tiles = [&]() {
#pragma unroll
        for (int it = 0; it < 4; it++) {
            int v = tid + it * 256;
            int m = v >> 3, kq = (v & 7) * 4;
            *(uint2*)&Ah_s[m * 40 + kq] = pAh[it];
            *(uint2*)&Al_s[m * 40 + kq] = pAl[it];
        }
#pragma unroll
        for (int it = 0; it < 2; it++) {
            int v = tid + it * 256;
            int n = v >> 3, kq = (v & 7) * 4;
            *(uint2*)&Wh_s[n * 40 + kq] = pWh[it];
            *(uint2*)&Wl_s[n * 40 + kq] = pWl[it];
        }
    };

    float acc[2][4][4];
#pragma unroll
    for (int a = 0; a < 2; a++)
#pragma unroll
        for (int b = 0; b < 4; b++)
#pragma unroll
            for (int c = 0; c < 4; c++) acc[a][b][c] = 0.f;

    fetch(0);
    for (int k0 = 0; k0 < DM; k0 += 32) {
        store_tiles();
        __syncthreads();
        if (k0 + 32 < DM) fetch(k0 + 32);

#pragma unroll
        for (int kc = 0; kc < 32; kc += 16) {
            unsigned ah[2][4], al[2][4];
#pragma unroll
            for (int mt = 0; mt < 2; mt++) {
                int r = warp_m * 32 + mt * 16 + lr;
                ah[mt][0] = *(unsigned*)&Ah_s[r * 40 + kc + lc2];
                ah[mt][1] = *(unsigned*)&Ah_s[(r + 8) * 40 + kc + lc2];
                ah[mt][2] = *(unsigned*)&Ah_s[r * 40 + kc + 8 + lc2];
                ah[mt][3] = *(unsigned*)&Ah_s[(r + 8) * 40 + kc + 8 + lc2];
                al[mt][0] = *(unsigned*)&Al_s[r * 40 + kc + lc2];
                al[mt][1] = *(unsigned*)&Al_s[(r + 8) * 40 + kc + lc2];
                al[mt][2] = *(unsigned*)&Al_s[r * 40 + kc + 8 + lc2];
                al[mt][3] = *(unsigned*)&Al_s[(r + 8) * 40 + kc + 8 + lc2];
            }
#pragma unroll
            for (int nt = 0; nt < 4; nt++) {
                int c = warp_n * 32 + nt * 8 + lr;
                unsigned bh0 = *(unsigned*)&Wh_s[c * 40 + kc + lc2];
                unsigned bh1 = *(unsigned*)&Wh_s[c * 40 + kc + 8 + lc2];
                unsigned bl0 = *(unsigned*)&Wl_s[c * 40 + kc + lc2];
                unsigned bl1 = *(unsigned*)&Wl_s[c * 40 + kc + 8 + lc2];
#pragma unroll
                for (int mt = 0; mt < 2; mt++) {
                    MMA_BF16(acc[mt][nt], ah[mt], bh0, bh1);
                    MMA_BF16(acc[mt][nt], ah[mt], bl0, bl1);
                    MMA_BF16(acc[mt][nt], al[mt], bh0, bh1);
                }
            }
        }
        __syncthreads();
    }

    const float qscale = (z == 0) ? 0.125f : 1.f;  // fold attn 1/sqrt(Dh) into Q
#pragma unroll
    for (int mt = 0; mt < 2; mt++) {
#pragma unroll
        for (int rr = 0; rr < 2; rr++) {
            int gm = row0 + warp_m * 32 + mt * 16 + lr + rr * 8;
            int b = gm >> 11, s = gm & 2047;
#pragma unroll
            for (int nt = 0; nt < 4; nt++) {
#pragma unroll
                for (int cc = 0; cc < 2; cc++) {
                    int gn = col0 + warp_n * 32 + nt * 8 + lc2 + cc;
                    int h = gn >> 6, d = gn & 63;
                    long long ci = (((long long)(b * HH + h)) * SS + s) * DH + d;
                    float val = acc[mt][nt][rr * 2 + cc] + gld(bias, gn, DM);
                    if (z == 2) {
                        gst(g_v, ci, QKV_ELEMS, val);
                    } else {
                        __nv_bfloat16 hh, ll;
                        f2bf2(val * qscale, hh, ll);
                        gstb((z == 0) ? g_qh : g_kh, ci, QKV_ELEMS, hh);
                        gstb((z == 0) ? g_ql : g_kl, ci, QKV_ELEMS, ll);
                    }
                }
            }
        }
    }
}

// ===========================================================================
// Output projection: pre-split ctx (A) + pre-split W_o, double-buffered.
// ===========================================================================
__global__ void __launch_bounds__(256) out_proj_mma_kernel(
    const float* __restrict__ bias, float* __restrict__ out)
{
    __shared__ __nv_bfloat16 Ah_s[128 * 40];
    __shared__ __nv_bfloat16 Al_s[128 * 40];
    __shared__ __nv_bfloat16 Wh_s[64 * 40];
    __shared__ __nv_bfloat16 Wl_s[64 * 40];

    const int tid = threadIdx.x;
    const int warp = tid >> 5, lane = tid & 31;
    const int warp_m = warp & 3, warp_n = warp >> 2;
    const int row0 = blockIdx.y * 128, col0 = blockIdx.x * 64;
    const int lr = lane >> 2, lc2 = (lane & 3) * 2;
    const long long woff = 3LL * W_ELEMS;  // W_o

    uint2 pAh[4], pAl[4], pWh[2], pWl[2];

    auto fetch = [&](int k0) {
#pragma unroll
        for (int it = 0; it < 4; it++) {
            int v = tid + it * 256;
            int m = v >> 3, kq = (v & 7) * 4;
            int gm = row0 + m;
            int gk = k0 + kq;
            int b = gm >> 11, s = gm & 2047;
            int h = gk >> 6, d = gk & 63;
            long long ai = (((long long)(b * HH + h)) * SS + s) * DH + d;
            pAh[it] = gldb4(g_ctxh, ai, QKV_ELEMS);
            pAl[it] = gldb4(g_ctxl, ai, QKV_ELEMS);
        }
#pragma unroll
        for (int it = 0; it < 2; it++) {
            int v = tid + it * 256;
            int n = v >> 3, kq = (v & 7) * 4;
            long long wi = woff + (long long)(col0 + n) * DM + k0 + kq;
            pWh[it] = gldb4(g_wsh, wi, 4 * W_ELEMS);
            pWl[it] = gldb4(g_wsl, wi, 4 * W_ELEMS);
        }
    };
    auto store_tiles = [&]() {
#pragma unroll
        for (int it = 0; it < 4; it++) {
            int v = tid + it * 256;
            int m = v >> 3, kq = (v & 7) * 4;
            *(uint2*)&Ah_s[m * 40 + kq] = pAh[it];
            *(uint2*)&Al_s[m * 40 + kq] = pAl[it];
        }
#pragma unroll
        for (int it = 0; it < 2; it++) {
            int v = tid + it * 256;
            int n = v >> 3, kq = (v & 7) * 4;
            *(uint2*)&Wh_s[n * 40 + kq] = pWh[it];
            *(uint2*)&Wl_s[n * 40 + kq] = pWl[it];
        }
    };

    float acc[2][4][4];
#pragma unroll
    for (int a = 0; a < 2; a++)
#pragma unroll
        for (int b = 0; b < 4; b++)
#pragma unroll
            for (int c = 0; c < 4; c++) acc[a][b][c] = 0.f;

    fetch(0);
    for (int k0 = 0; k0 < DM; k0 += 32) {
        store_tiles();
        __syncthreads();
        if (k0 + 32 < DM) fetch(k0 + 32);

#pragma unroll
        for (int kc = 0; kc < 32; kc += 16) {
            unsigned ah[2][4], al[2][4];
#pragma unroll
            for (int mt = 0; mt < 2; mt++) {
                int r = warp_m * 32 + mt * 16 + lr;
                ah[mt][0] = *(unsigned*)&Ah_s[r * 40 + kc + lc2];
                ah[mt][1] = *(unsigned*)&Ah_s[(r + 8) * 40 + kc + lc2];
                ah[mt][2] = *(unsigned*)&Ah_s[r * 40 + kc + 8 + lc2];
                ah[mt][3] = *(unsigned*)&Ah_s[(r + 8) * 40 + kc + 8 + lc2];
                al[mt][0] = *(unsigned*)&Al_s[r * 40 + kc + lc2];
                al[mt][1] = *(unsigned*)&Al_s[(r + 8) * 40 + kc + lc2];
                al[mt][2] = *(unsigned*)&Al_s[r * 40 + kc + 8 + lc2];
                al[mt][3] = *(unsigned*)&Al_s[(r + 8) * 40 + kc + 8 + lc2];
            }
#pragma unroll
            for (int nt = 0; nt < 4; nt++) {
                int c = warp_n * 32 + nt * 8 + lr;
                unsigned bh0 = *(unsigned*)&Wh_s[c * 40 + kc + lc2];
                unsigned bh1 = *(unsigned*)&Wh_s[c * 40 + kc + 8 + lc2];
                unsigned bl0 = *(unsigned*)&Wl_s[c * 40 + kc + lc2];
                unsigned bl1 = *(unsigned*)&Wl_s[c * 40 + kc + 8 + lc2];
#pragma unroll
                for (int mt = 0; mt < 2; mt++) {
                    MMA_BF16(acc[mt][nt], ah[mt], bh0, bh1);
                    MMA_BF16(acc[mt][nt], ah[mt], bl0, bl1);
                    MMA_BF16(acc[mt][nt], al[mt], bh0, bh1);
                }
            }
        }
        __syncthreads();
    }

#pragma unroll
    for (int mt = 0; mt < 2; mt++) {
#pragma unroll
        for (int rr = 0; rr < 2; rr++) {
            int gm = row0 + warp_m * 32 + mt * 16 + lr + rr * 8;
#pragma unroll
            for (int nt = 0; nt < 4; nt++) {
                int gn = col0 + warp_n * 32 + nt * 8 + lc2;
                gst2(out, (long long)gm * DM + gn, OUT_ELEMS,
                     acc[mt][nt][rr * 2 + 0] + gld(bias, gn, DM),
                     acc[mt][nt][rr * 2 + 1] + gld(bias, gn + 1, DM));
            }
        }
    }
}

// ===========================================================================
// Scores via bf16x3 mma (Q pre-scaled; paired stores).
// ===========================================================================
#define SCORES_SMEM 73728

__global__ void __launch_bounds__(256) scores_mma_kernel(float* __restrict__ attn)
{
    extern __shared__ __align__(16) char smraw[];
    __nv_bfloat16* Qh_s = (__nv_bfloat16*)smraw;
    __nv_bfloat16* Ql_s = (__nv_bfloat16*)(smraw + 18432);
    __nv_bfloat16* Kh_s = (__nv_bfloat16*)(smraw + 36864);
    __nv_bfloat16* Kl_s = (__nv_bfloat16*)(smraw + 55296);

    const int tid = threadIdx.x;
    const int warp = tid >> 5;
    const int lane = tid & 31;
    const int warp_m = warp & 3;
    const int warp_n = warp >> 2;
    const int bh = blockIdx.z;
    const int row0 = blockIdx.y * 128;
    const int col0 = blockIdx.x * 128;
    const long long hb = (long long)bh * SS * DH;

#pragma unroll
    for (int it = 0; it < 8; it++) {
        int v = tid + it * 256;
        int m = v >> 4;
        int kq = (v & 15) * 4;
        long long qi = hb + (long long)(row0 + m) * DH + kq;
        *(uint2*)&Qh_s[m * 72 + kq] = gldb4(g_qh, qi, QKV_ELEMS);
        *(uint2*)&Ql_s[m * 72 + kq] = gldb4(g_ql, qi, QKV_ELEMS);
        long long ki = hb + (long long)(col0 + m) * DH + kq;
        *(uint2*)&Kh_s[m * 72 + kq] = gldb4(g_kh, ki, QKV_ELEMS);
        *(uint2*)&Kl_s[m * 72 + kq] = gldb4(g_kl, ki, QKV_ELEMS);
    }
    __syncthreads();

    const int lr = lane >> 2;
    const int lc2 = (lane & 3) * 2;

    float acc[2][8][4];
#pragma unroll
    for (int a = 0; a < 2; a++)
#pragma unroll
        for (int b = 0; b < 8; b++)
#pragma unroll
            for (int c = 0; c < 4; c++) acc[a][b][c] = 0.f;

#pragma unroll
    for (int kc = 0; kc < 4; kc++) {
        int k0 = kc * 16;
        unsigned ah[2][4], al[2][4];
#pragma unroll
        for (int mt = 0; mt < 2; mt++) {
            int r = warp_m * 32 + mt * 16 + lr;
            ah[mt][0] = *(unsigned*)&Qh_s[r * 72 + k0 + lc2];
            ah[mt][1] = *(unsigned*)&Qh_s[(r + 8) * 72 + k0 + lc2];
            ah[mt][2] = *(unsigned*)&Qh_s[r * 72 + k0 + 8 + lc2];
            ah[mt][3] = *(unsigned*)&Qh_s[(r + 8) * 72 + k0 + 8 + lc2];
            al[mt][0] = *(unsigned*)&Ql_s[r * 72 + k0 + lc2];
            al[mt][1] = *(unsigned*)&Ql_s[(r + 8) * 72 + k0 + lc2];
            al[mt][2] = *(unsigned*)&Ql_s[r * 72 + k0 + 8 + lc2];
            al[mt][3] = *(unsigned*)&Ql_s[(r + 8) * 72 + k0 + 8 + lc2];
        }
#pragma unroll
        for (int nt = 0; nt < 8; nt++) {
            int c = warp_n * 64 + nt * 8 + lr;
            unsigned bh0 = *(unsigned*)&Kh_s[c * 72 + k0 + lc2];
            unsigned bh1 = *(unsigned*)&Kh_s[c * 72 + k0 + 8 + lc2];
            unsigned bl0 = *(unsigned*)&Kl_s[c * 72 + k0 + lc2];
            unsigned bl1 = *(unsigned*)&Kl_s[c * 72 + k0 + 8 + lc2];
#pragma unroll
            for (int mt = 0; mt < 2; mt++) {
                MMA_BF16(acc[mt][nt], ah[mt], bh0, bh1);
                MMA_BF16(acc[mt][nt], ah[mt], bl0, bl1);
                MMA_BF16(acc[mt][nt], al[mt], bh0, bh1);
            }
        }
    }

#pragma unroll
    for (int mt = 0; mt < 2; mt++) {
        int mrow = row0 + warp_m * 32 + mt * 16 + lr;
#pragma unroll
        for (int nt = 0; nt < 8; nt++) {
            int ncol = col0 + warp_n * 64 + nt * 8 + lc2;
            long long i0 = ((long long)bh * SS + mrow) * SS + ncol;
            long long i2 = ((long long)bh * SS + mrow + 8) * SS + ncol;
            gst2(attn, i0, ATTN_ELEMS, acc[mt][nt][0], acc[mt][nt][1]);
            gst2(attn, i2, ATTN_ELEMS, acc[mt][nt][2], acc[mt][nt][3]);
        }
    }
}

// ===========================================================================
// Row softmax over 2048 cols (unchanged).
// ===========================================================================
__global__ void __launch_bounds__(256) softmax_kernel(float* __restrict__ attn)
{
    __shared__ float red[8];
    const long long rbase = (long long)blockIdx.x * SS;
    const int tid = threadIdx.x;

    float4 v0 = gld4(attn, rbase + tid * 4, ATTN_ELEMS);
    float4 v1 = gld4(attn, rbase + 1024 + tid * 4, ATTN_ELEMS);

    float m = fmaxf(fmaxf(fmaxf(v0.x, v0.y), fmaxf(v0.z, v0.w)),
                    fmaxf(fmaxf(v1.x, v1.y), fmaxf(v1.z, v1.w)));
#pragma unroll
    for (int o = 16; o > 0; o >>= 1) m = fmaxf(m, __shfl_xor_sync(0xFFFFFFFFu, m, o));
    if ((tid & 31) == 0) red[tid >> 5] = m;
    __syncthreads();
    m = red[0];
#pragma unroll
    for (int w = 1; w < 8; w++) m = fmaxf(m, red[w]);
    __syncthreads();

    v0.x = __expf(v0.x - m); v0.y = __expf(v0.y - m);
    v0.z = __expf(v0.z - m); v0.w = __expf(v0.w - m);
    v1.x = __expf(v1.x - m); v1.y = __expf(v1.y - m);
    v1.z = __expf(v1.z - m); v1.w = __expf(v1.w - m);
    float s = v0.x + v0.y + v0.z + v0.w + v1.x + v1.y + v1.z + v1.w;
#pragma unroll
    for (int o = 16; o > 0; o >>= 1) s += __shfl_xor_sync(0xFFFFFFFFu, s, o);
    if ((tid & 31) == 0) red[tid >> 5] = s;
    __syncthreads();
    s = red[0];
#pragma unroll
    for (int w = 1; w < 8; w++) s += red[w];

    float inv = 1.f / s;
    v0.x *= inv; v0.y *= inv; v0.z *= inv; v0.w *= inv;
    v1.x *= inv; v1.y *= inv; v1.z *= inv; v1.w *= inv;

    long long i0 = rbase + tid * 4;
    long long i1 = rbase + 1024 + tid * 4;
    if (i0 + 3 < ATTN_ELEMS) *(float4*)(attn + i0) = v0;
    if (i1 + 3 < ATTN_ELEMS) *(float4*)(attn + i1) = v1;
}

// ===========================================================================
// AV via bf16x3 mma (unchanged; ctx emitted bf16 hi/lo).
// ===========================================================================
#define AV_SMEM 55296

__global__ void __launch_bounds__(256) av_mma_kernel(const float* __restrict__ attn)
{
    extern __shared__ __align__(16) char smraw[];
    __nv_bfloat16* Ph_s  = (__nv_bfloat16*)smraw;
    __nv_bfloat16* Pl_s  = (__nv_bfloat16*)(smraw + 18432);
    __nv_bfloat16* Vth_s = (__nv_bfloat16*)(smraw + 36864);
    __nv_bfloat16* Vtl_s = (__nv_bfloat16*)(smraw + 46080);

    const int tid = threadIdx.x;
    const int warp = tid >> 5;
    const int lane = tid & 31;
    const int warp_m = warp & 3;
    const int warp_n = warp >> 2;
    const int bh = blockIdx.y;
    const int row0 = blockIdx.x * 128;
    const long long pbase = (long long)bh * SS * SS;
    const long long vbase = (long long)bh * SS * DH;

    const int lr = lane >> 2;
    const int lc2 = (lane & 3) * 2;

    float acc[2][4][4];
#pragma unroll
    for (int a = 0; a < 2; a++)
#pragma unroll
        for (int b = 0; b < 4; b++)
#pragma unroll
            for (int c = 0; c < 4; c++) acc[a][b][c] = 0.f;

    for (int kk = 0; kk < SS; kk += 64) {
#pragma unroll
        for (int it = 0; it < 8; it++) {
            int v = tid + it * 256;
            int m = v >> 4;
            int kq = (v & 15) * 4;
            float4 p = gld4(attn, pbase + (long long)(row0 + m) * SS + kk + kq, ATTN_ELEMS);
            uint2 h, l;
            split4(p, h, l);
            *(uint2*)&Ph_s[m * 72 + kq] = h;
            *(uint2*)&Pl_s[m * 72 + kq] = l;
        }
#pragma unroll
        for (int it = 0; it < 4; it++) {
            int v = tid + it * 256;
            int k = v >> 4;
            int dq = (v & 15) * 4;
            float4 vv = gld4(g_v, vbase + (long long)(kk + k) * DH + dq, QKV_ELEMS);
            __nv_bfloat16 h, l;
            f2bf2(vv.x, h, l); Vth_s[(dq + 0) * 72 + k] = h; Vtl_s[(dq + 0) * 72 + k] = l;
            f2bf2(vv.y, h, l); Vth_s[(dq + 1) * 72 + k] = h; Vtl_s[(dq + 1) * 72 + k] = l;
            f2bf2(vv.z, h, l); Vth_s[(dq + 2) * 72 + k] = h; Vtl_s[(dq + 2) * 72 + k] = l;
            f2bf2(vv.w, h, l); Vth_s[(dq + 3) * 72 + k] = h; Vtl_s[(dq + 3) * 72 + k] = l;
        }
        __syncthreads();

#pragma unroll
        for (int kc = 0; kc < 4; kc++) {
            int k0 = kc * 16;
            unsigned ah[2][4], al[2][4];
#pragma unroll
            for (int mt = 0; mt < 2; mt++) {
                int r = warp_m * 32 + mt * 16 + lr;
                ah[mt][0] = *(unsigned*)&Ph_s[r * 72 + k0 + lc2];
                ah[mt][1] = *(unsigned*)&Ph_s[(r + 8) * 72 + k0 + lc2];
                ah[mt][2] = *(unsigned*)&Ph_s[r * 72 + k0 + 8 + lc2];
                ah[mt][3] = *(unsigned*)&Ph_s[(r + 8) * 72 + k0 + 8 + lc2];
                al[mt][0] = *(unsigned*)&Pl_s[r * 72 + k0 + lc2];
                al[mt][1] = *(unsigned*)&Pl_s[(r + 8) * 72 + k0 + lc2];
                al[mt][2] = *(unsigned*)&Pl_s[r * 72 + k0 + 8 + lc2];
                al[mt][3] = *(unsigned*)&Pl_s[(r + 8) * 72 + k0 + 8 + lc2];
            }
#pragma unroll
            for (int nt = 0; nt < 4; nt++) {
                int c = warp_n * 32 + nt * 8 + lr;
                unsigned bh0 = *(unsigned*)&Vth_s[c * 72 + k0 + lc2];
                unsigned bh1 = *(unsigned*)&Vth_s[c * 72 + k0 + 8 + lc2];
                unsigned bl0 = *(unsigned*)&Vtl_s[c * 72 + k0 + lc2];
                unsigned bl1 = *(unsigned*)&Vtl_s[c * 72 + k0 + 8 + lc2];
#pragma unroll
                for (int mt = 0; mt < 2; mt++) {
                    MMA_BF16(acc[mt][nt], ah[mt], bh0, bh1);
                    MMA_BF16(acc[mt][nt], ah[mt], bl0, bl1);
                    MMA_BF16(acc[mt][nt], al[mt], bh0, bh1);
                }
            }
        }
        __syncthreads();
    }

#pragma unroll
    for (int mt = 0; mt < 2; mt++) {
#pragma unroll
        for (int rr = 0; rr < 2; rr++) {
            int mrow = row0 + warp_m * 32 + mt * 16 + lr + rr * 8;
#pragma unroll
            for (int nt = 0; nt < 4; nt++) {
#pragma unroll
                for (int cc = 0; cc < 2; cc++) {
                    int dcol = warp_n * 32 + nt * 8 + lc2 + cc;
                    long long ci = vbase + (long long)mrow * DH + dcol;
                    __nv_bfloat16 h, l;
                    f2bf2(acc[mt][nt][rr * 2 + cc], h, l);
                    gstb(g_ctxh, ci, QKV_ELEMS, h);
                    gstb(g_ctxl, ci, QKV_ELEMS, l);
                }
            }
        }
    }
}

// ---------------------------------------------------------------------------
static bool s_capturing_probe()
{
    cudaStreamCaptureStatus st = cudaStreamCaptureStatusNone;
    cudaError_t e = cudaStreamIsCapturing(0, &st);
    if (e != cudaSuccess) { cudaGetLastError(); return true; }
    return st != cudaStreamCaptureStatusNone;
}

static void diag(const char* name, bool capturing)
{
    if (capturing) return;  // launches only during graph capture
    cudaError_t e = cudaDeviceSynchronize();
    fprintf(stderr, "[klaunch] %s: %s\n", name, cudaGetErrorString(e));
    cudaGetLastError();
}

extern "C" void kernel_launch(void* const* d_in, const int* in_sizes, int n_in,
                              void* d_out, int out_size)
{
    const float* query = (const float*)d_in[0];
    const float* key   = (const float*)d_in[1];
    const float* value = (const float*)d_in[2];
    const float* W_q   = (const float*)d_in[3];
    const float* b_q   = (const float*)d_in[4];
    const float* W_k   = (const float*)d_in[5];
    const float* b_k   = (const float*)d_in[6];
    const float* W_v   = (const float*)d_in[7];
    const float* b_v   = (const float*)d_in[8];
    const float* W_o   = (const float*)d_in[9];
    const float* b_o   = (const float*)d_in[10];

    float* out  = (float*)d_out;
    float* attn = out + OUT_ELEMS;  // confirmed: out_size == OUT_ELEMS + ATTN_ELEMS

    const bool capturing = s_capturing_probe();

    cudaFuncSetAttribute(scores_mma_kernel,
                         cudaFuncAttributeMaxDynamicSharedMemorySize, SCORES_SMEM);
    cudaFuncSetAttribute(av_mma_kernel,
                         cudaFuncAttributeMaxDynamicSharedMemorySize, AV_SMEM);

    dim3 gSplit(1024, 7);
    dim3 gProj(DM / 64, MM / 128, 3);           // (12, 32, 3) fused q/k/v
    dim3 gOutProj(DM / 64, MM / 128);           // (12, 32)
    dim3 gScores(SS / 128, SS / 128, BB * HH);  // (16, 16, 24)
    dim3 gAV(SS / 128, BB * HH);                // (16, 24)

    split_all_kernel<<<gSplit, 256>>>(query, key, value, W_q, W_k, W_v, W_o);
    diag("split", capturing);

    proj_mma_kernel<<<gProj, 256>>>(b_q, b_k, b_v);
    diag("proj_qkv", capturing);

    scores_mma_kernel<<<gScores, 256, SCORES_SMEM>>>(attn);
    diag("scores_mma", capturing);

    softmax_kernel<<<BB * HH * SS, 256>>>(attn);
    diag("softmax", capturing);

    av_mma_kernel<<<gAV, 256, AV_SMEM>>>(attn);
    diag("av_mma", capturing);

    out_proj_mma_kernel<<<gOutProj, 256>>>(b_o, out);
    diag("out_proj", capturing);
}

// round 16
// speedup vs baseline: 1.3862x; 1.3862x over previous
#include <cuda_runtime.h>
#include <cuda_bf16.h>
#include <cstdio>

#define BB 2
#define HH 12
#define SS 2048
#define DH 64
#define DM 768
#define MM (BB * SS)                                   // 4096
#define ACT_ELEMS ((long long)BB * SS * DM)            // 3,145,728
#define QKV_ELEMS ((long long)BB * HH * SS * DH)       // 3,145,728
#define W_ELEMS ((long long)DM * DM)                   // 589,824
#define OUT_ELEMS ((long long)BB * SS * DM)            // 3,145,728
#define ATTN_ELEMS ((long long)BB * HH * SS * SS)      // 100,663,296

// Static device scratch.
__device__ __align__(16) float g_v[3145728];
__device__ __align__(16) __nv_bfloat16 g_qh[3145728];
__device__ __align__(16) __nv_bfloat16 g_ql[3145728];
__device__ __align__(16) __nv_bfloat16 g_kh[3145728];
__device__ __align__(16) __nv_bfloat16 g_kl[3145728];
__device__ __align__(16) __nv_bfloat16 g_ctxh[3145728];
__device__ __align__(16) __nv_bfloat16 g_ctxl[3145728];
// Pre-split activations (query|key|value) and weights (W_q|W_k|W_v|W_o).
__device__ __align__(16) __nv_bfloat16 g_axh[3 * 3145728];
__device__ __align__(16) __nv_bfloat16 g_axl[3 * 3145728];
__device__ __align__(16) __nv_bfloat16 g_wsh[4 * 589824];
__device__ __align__(16) __nv_bfloat16 g_wsl[4 * 589824];

// Guarded accessors (proven shell).
__device__ __forceinline__ float gld(const float* __restrict__ p, long long i, long long n) {
    return (i >= 0 && i < n) ? __ldg(p + i) : 0.f;
}
__device__ __forceinline__ void gst(float* __restrict__ p, long long i, long long n, float v) {
    if (i >= 0 && i < n) p[i] = v;
}
__device__ __forceinline__ void gst2(float* __restrict__ p, long long i, long long n, float a, float b) {
    if (i >= 0 && i + 1 < n) { float2 t = {a, b}; *(float2*)(p + i) = t; }
}
__device__ __forceinline__ float4 gld4(const float* __restrict__ p, long long i, long long n) {
    if (i >= 0 && i + 3 < n) return __ldg((const float4*)(p + i));
    float4 z = {0.f, 0.f, 0.f, 0.f};
    return z;
}
__device__ __forceinline__ void gstb(__nv_bfloat16* p, long long i, long long n, __nv_bfloat16 v) {
    if (i >= 0 && i < n) p[i] = v;
}
__device__ __forceinline__ uint2 gldb4(const __nv_bfloat16* __restrict__ p, long long i, long long n) {
    if (i >= 0 && i + 3 < n) return *(const uint2*)(p + i);
    return make_uint2(0u, 0u);
}
__device__ __forceinline__ void gstb4(__nv_bfloat16* p, long long i, long long n, uint2 v) {
    if (i >= 0 && i + 3 < n) *(uint2*)(p + i) = v;
}

// bf16 hi/lo split.
__device__ __forceinline__ void f2bf2(float x, __nv_bfloat16& h, __nv_bfloat16& l) {
    h = __float2bfloat16_rn(x);
    l = __float2bfloat16_rn(x - __bfloat162float(h));
}
__device__ __forceinline__ void split4(float4 x, uint2& h, uint2& l) {
    __nv_bfloat16 h0, l0, h1, l1, h2, l2, h3, l3;
    f2bf2(x.x, h0, l0); f2bf2(x.y, h1, l1);
    f2bf2(x.z, h2, l2); f2bf2(x.w, h3, l3);
    h.x = ((unsigned)__bfloat16_as_ushort(h1) << 16) | __bfloat16_as_ushort(h0);
    h.y = ((unsigned)__bfloat16_as_ushort(h3) << 16) | __bfloat16_as_ushort(h2);
    l.x = ((unsigned)__bfloat16_as_ushort(l1) << 16) | __bfloat16_as_ushort(l0);
    l.y = ((unsigned)__bfloat16_as_ushort(l3) << 16) | __bfloat16_as_ushort(l2);
}

#define MMA_BF16(d, a, b0v, b1v)                                                 \
    asm volatile(                                                                \
        "mma.sync.aligned.m16n8k16.row.col.f32.bf16.bf16.f32 "                   \
        "{%0,%1,%2,%3}, {%4,%5,%6,%7}, {%8,%9}, {%0,%1,%2,%3};"                  \
        : "+f"((d)[0]), "+f"((d)[1]), "+f"((d)[2]), "+f"((d)[3])                 \
        : "r"((a)[0]), "r"((a)[1]), "r"((a)[2]), "r"((a)[3]), "r"(b0v), "r"(b1v));

// ===========================================================================
// Pre-split: fp32 -> bf16 hi/lo for 3 activations + 4 weights.
// ===========================================================================
__global__ void __launch_bounds__(256) split_all_kernel(
    const float* __restrict__ q, const float* __restrict__ k,
    const float* __restrict__ v, const float* __restrict__ wq,
    const float* __restrict__ wk, const float* __restrict__ wv,
    const float* __restrict__ wo)
{
    const int t = blockIdx.y;
    const float* src = (t == 0) ? q : (t == 1) ? k : (t == 2) ? v
                     : (t == 3) ? wq : (t == 4) ? wk : (t == 5) ? wv : wo;
    const long long nelem = (t < 3) ? ACT_ELEMS : W_ELEMS;
    const long long nq = nelem >> 2;
    __nv_bfloat16* dh;
    __nv_bfloat16* dl;
    long long off;
    long long dn;
    if (t < 3) { dh = g_axh; dl = g_axl; off = (long long)t * ACT_ELEMS; dn = 3 * ACT_ELEMS; }
    else       { dh = g_wsh; dl = g_wsl; off = (long long)(t - 3) * W_ELEMS; dn = 4 * W_ELEMS; }

    for (long long i = (long long)blockIdx.x * 256 + threadIdx.x; i < nq;
         i += (long long)gridDim.x * 256) {
        float4 x = gld4(src, i * 4, nelem);
        uint2 h, l;
        split4(x, h, l);
        gstb4(dh, off + i * 4, dn, h);
        gstb4(dl, off + i * 4, dn, l);
    }
}

// ===========================================================================
// Projection GEMM via bf16x3 mma (compile-time DSTSEL, separate launches).
// Q (DSTSEL=0) epilogue pre-scales by 0.125 (exact pow2).
// Block 128m x 64n, 8 warps (32x32), BK=32, register double-buffer.
// ===========================================================================
template <int DSTSEL>
__global__ void __launch_bounds__(256) proj_mma_kernel(const float* __restrict__ bias)
{
    __shared__ __nv_bfloat16 Ah_s[128 * 40];
    __shared__ __nv_bfloat16 Al_s[128 * 40];
    __shared__ __nv_bfloat16 Wh_s[64 * 40];
    __shared__ __nv_bfloat16 Wl_s[64 * 40];

    const int tid = threadIdx.x;
    const int warp = tid >> 5, lane = tid & 31;
    const int warp_m = warp & 3, warp_n = warp >> 2;
    const int row0 = blockIdx.y * 128, col0 = blockIdx.x * 64;
    const int lr = lane >> 2, lc2 = (lane & 3) * 2;
    const long long aoff = (long long)DSTSEL * ACT_ELEMS;
    const long long woff = (long long)DSTSEL * W_ELEMS;

    uint2 pAh[4], pAl[4], pWh[2], pWl[2];

    auto fetch = [&](int k0) {
#pragma unroll
        for (int it = 0; it < 4; it++) {
            int v = tid + it * 256;
            int m = v >> 3, kq = (v & 7) * 4;
            long long ai = aoff + (long long)(row0 + m) * DM + k0 + kq;
            pAh[it] = gldb4(g_axh, ai, 3 * ACT_ELEMS);
            pAl[it] = gldb4(g_axl, ai, 3 * ACT_ELEMS);
        }
#pragma unroll
        for (int it = 0; it < 2; it++) {
            int v = tid + it * 256;
            int n = v >> 3, kq = (v & 7) * 4;
            long long wi = woff + (long long)(col0 + n) * DM + k0 + kq;
            pWh[it] = gldb4(g_wsh, wi, 4 * W_ELEMS);
            pWl[it] = gldb4(g_wsl, wi, 4 * W_ELEMS);
        }
    };
    auto store_tiles = [&]() {
#pragma unroll
        for (int it = 0; it < 4; it++) {
            int v = tid + it * 256;
            int m = v >> 3, kq = (v & 7) * 4;
            *(uint2*)&Ah_s[m * 40 + kq] = pAh[it];
            *(uint2*)&Al_s[m * 40 + kq] = pAl[it];
        }
#pragma unroll
        for (int it = 0; it < 2; it++) {
            int v = tid + it * 256;
            int n = v >> 3, kq = (v & 7) * 4;
            *(uint2*)&Wh_s[n * 40 + kq] = pWh[it];
            *(uint2*)&Wl_s[n * 40 + kq] = pWl[it];
        }
    };

    float acc[2][4][4];
#pragma unroll
    for (int a = 0; a < 2; a++)
#pragma unroll
        for (int b = 0; b < 4; b++)
#pragma unroll
            for (int c = 0; c < 4; c++) acc[a][b][c] = 0.f;

    fetch(0);
    for (int k0 = 0; k0 < DM; k0 += 32) {
        store_tiles();
        __syncthreads();
        if (k0 + 32 < DM) fetch(k0 + 32);

#pragma unroll
        for (int kc = 0; kc < 32; kc += 16) {
            unsigned ah[2][4], al[2][4];
#pragma unroll
            for (int mt = 0; mt < 2; mt++) {
                int r = warp_m * 32 + mt * 16 + lr;
                ah[mt][0] = *(unsigned*)&Ah_s[r * 40 + kc + lc2];
                ah[mt][1] = *(unsigned*)&Ah_s[(r + 8) * 40 + kc + lc2];
                ah[mt][2] = *(unsigned*)&Ah_s[r * 40 + kc + 8 + lc2];
                ah[mt][3] = *(unsigned*)&Ah_s[(r + 8) * 40 + kc + 8 + lc2];
                al[mt][0] = *(unsigned*)&Al_s[r * 40 + kc + lc2];
                al[mt][1] = *(unsigned*)&Al_s[(r + 8) * 40 + kc + lc2];
                al[mt][2] = *(unsigned*)&Al_s[r * 40 + kc + 8 + lc2];
                al[mt][3] = *(unsigned*)&Al_s[(r + 8) * 40 + kc + 8 + lc2];
            }
#pragma unroll
            for (int nt = 0; nt < 4; nt++) {
                int c = warp_n * 32 + nt * 8 + lr;
                unsigned bh0 = *(unsigned*)&Wh_s[c * 40 + kc + lc2];
                unsigned bh1 = *(unsigned*)&Wh_s[c * 40 + kc + 8 + lc2];
                unsigned bl0 = *(unsigned*)&Wl_s[c * 40 + kc + lc2];
                unsigned bl1 = *(unsigned*)&Wl_s[c * 40 + kc + 8 + lc2];
#pragma unroll
                for (int mt = 0; mt < 2; mt++) {
                    MMA_BF16(acc[mt][nt], ah[mt], bh0, bh1);
                    MMA_BF16(acc[mt][nt], ah[mt], bl0, bl1);
                    MMA_BF16(acc[mt][nt], al[mt], bh0, bh1);
                }
            }
        }
        __syncthreads();
    }

#pragma unroll
    for (int mt = 0; mt < 2; mt++) {
#pragma unroll
        for (int rr = 0; rr < 2; rr++) {
            int gm = row0 + warp_m * 32 + mt * 16 + lr + rr * 8;
            int b = gm >> 11, s = gm & 2047;
#pragma unroll
            for (int nt = 0; nt < 4; nt++) {
#pragma unroll
                for (int cc = 0; cc < 2; cc++) {
                    int gn = col0 + warp_n * 32 + nt * 8 + lc2 + cc;
                    int h = gn >> 6, d = gn & 63;
                    long long ci = (((long long)(b * HH + h)) * SS + s) * DH + d;
                    float val = acc[mt][nt][rr * 2 + cc] + gld(bias, gn, DM);
                    if (DSTSEL == 2) {
                        gst(g_v, ci, QKV_ELEMS, val);
                    } else {
                        if (DSTSEL == 0) val *= 0.125f;  // fold 1/sqrt(Dh) into Q
                        __nv_bfloat16 hh, ll;
                        f2bf2(val, hh, ll);
                        gstb((DSTSEL == 0) ? g_qh : g_kh, ci, QKV_ELEMS, hh);
                        gstb((DSTSEL == 0) ? g_ql : g_kl, ci, QKV_ELEMS, ll);
                    }
                }
            }
        }
    }
}

// ===========================================================================
// Output projection: pre-split ctx (A) + pre-split W_o, double-buffered.
// ===========================================================================
__global__ void __launch_bounds__(256) out_proj_mma_kernel(
    const float* __restrict__ bias, float* __restrict__ out)
{
    __shared__ __nv_bfloat16 Ah_s[128 * 40];
    __shared__ __nv_bfloat16 Al_s[128 * 40];
    __shared__ __nv_bfloat16 Wh_s[64 * 40];
    __shared__ __nv_bfloat16 Wl_s[64 * 40];

    const int tid = threadIdx.x;
    const int warp = tid >> 5, lane = tid & 31;
    const int warp_m = warp & 3, warp_n = warp >> 2;
    const int row0 = blockIdx.y * 128, col0 = blockIdx.x * 64;
    const int lr = lane >> 2, lc2 = (lane & 3) * 2;
    const long long woff = 3LL * W_ELEMS;  // W_o

    uint2 pAh[4], pAl[4], pWh[2], pWl[2];

    auto fetch = [&](int k0) {
#pragma unroll
        for (int it = 0; it < 4; it++) {
            int v = tid + it * 256;
            int m = v >> 3, kq = (v & 7) * 4;
            int gm = row0 + m;
            int gk = k0 + kq;
            int b = gm >> 11, s = gm & 2047;
            int h = gk >> 6, d = gk & 63;
            long long ai = (((long long)(b * HH + h)) * SS + s) * DH + d;
            pAh[it] = gldb4(g_ctxh, ai, QKV_ELEMS);
            pAl[it] = gldb4(g_ctxl, ai, QKV_ELEMS);
        }
#pragma unroll
        for (int it = 0; it < 2; it++) {
            int v = tid + it * 256;
            int n = v >> 3, kq = (v & 7) * 4;
            long long wi = woff + (long long)(col0 + n) * DM + k0 + kq;
            pWh[it] = gldb4(g_wsh, wi, 4 * W_ELEMS);
            pWl[it] = gldb4(g_wsl, wi, 4 * W_ELEMS);
        }
    };
    auto store_tiles = [&]() {
#pragma unroll
        for (int it = 0; it < 4; it++) {
            int v = tid + it * 256;
            int m = v >> 3, kq = (v & 7) * 4;
            *(uint2*)&Ah_s[m * 40 + kq] = pAh[it];
            *(uint2*)&Al_s[m * 40 + kq] = pAl[it];
        }
#pragma unroll
        for (int it = 0; it < 2; it++) {
            int v = tid + it * 256;
            int n = v >> 3, kq = (v & 7) * 4;
            *(uint2*)&Wh_s[n * 40 + kq] = pWh[it];
            *(uint2*)&Wl_s[n * 40 + kq] = pWl[it];
        }
    };

    float acc[2][4][4];
#pragma unroll
    for (int a = 0; a < 2; a++)
#pragma unroll
        for (int b = 0; b < 4; b++)
#pragma unroll
            for (int c = 0; c < 4; c++) acc[a][b][c] = 0.f;

    fetch(0);
    for (int k0 = 0; k0 < DM; k0 += 32) {
        store_tiles();
        __syncthreads();
        if (k0 + 32 < DM) fetch(k0 + 32);

#pragma unroll
        for (int kc = 0; kc < 32; kc += 16) {
            unsigned ah[2][4], al[2][4];
#pragma unroll
            for (int mt = 0; mt < 2; mt++) {
                int r = warp_m * 32 + mt * 16 + lr;
                ah[mt][0] = *(unsigned*)&Ah_s[r * 40 + kc + lc2];
                ah[mt][1] = *(unsigned*)&Ah_s[(r + 8) * 40 + kc + lc2];
                ah[mt][2] = *(unsigned*)&Ah_s[r * 40 + kc + 8 + lc2];
                ah[mt][3] = *(unsigned*)&Ah_s[(r + 8) * 40 + kc + 8 + lc2];
                al[mt][0] = *(unsigned*)&Al_s[r * 40 + kc + lc2];
                al[mt][1] = *(unsigned*)&Al_s[(r + 8) * 40 + kc + lc2];
                al[mt][2] = *(unsigned*)&Al_s[r * 40 + kc + 8 + lc2];
                al[mt][3] = *(unsigned*)&Al_s[(r + 8) * 40 + kc + 8 + lc2];
            }
#pragma unroll
            for (int nt = 0; nt < 4; nt++) {
                int c = warp_n * 32 + nt * 8 + lr;
                unsigned bh0 = *(unsigned*)&Wh_s[c * 40 + kc + lc2];
                unsigned bh1 = *(unsigned*)&Wh_s[c * 40 + kc + 8 + lc2];
                unsigned bl0 = *(unsigned*)&Wl_s[c * 40 + kc + lc2];
                unsigned bl1 = *(unsigned*)&Wl_s[c * 40 + kc + 8 + lc2];
#pragma unroll
                for (int mt = 0; mt < 2; mt++) {
                    MMA_BF16(acc[mt][nt], ah[mt], bh0, bh1);
                    MMA_BF16(acc[mt][nt], ah[mt], bl0, bl1);
                    MMA_BF16(acc[mt][nt], al[mt], bh0, bh1);
                }
            }
        }
        __syncthreads();
    }

#pragma unroll
    for (int mt = 0; mt < 2; mt++) {
#pragma unroll
        for (int rr = 0; rr < 2; rr++) {
            int gm = row0 + warp_m * 32 + mt * 16 + lr + rr * 8;
#pragma unroll
            for (int nt = 0; nt < 4; nt++) {
                int gn = col0 + warp_n * 32 + nt * 8 + lc2;
                gst2(out, (long long)gm * DM + gn, OUT_ELEMS,
                     acc[mt][nt][rr * 2 + 0] + gld(bias, gn, DM),
                     acc[mt][nt][rr * 2 + 1] + gld(bias, gn + 1, DM));
            }
        }
    }
}

// ===========================================================================
// Scores via bf16x3 mma (Q pre-scaled; paired stores).
// ===========================================================================
#define SCORES_SMEM 73728

__global__ void __launch_bounds__(256) scores_mma_kernel(float* __restrict__ attn)
{
    extern __shared__ __align__(16) char smraw[];
    __nv_bfloat16* Qh_s = (__nv_bfloat16*)smraw;
    __nv_bfloat16* Ql_s = (__nv_bfloat16*)(smraw + 18432);
    __nv_bfloat16* Kh_s = (__nv_bfloat16*)(smraw + 36864);
    __nv_bfloat16* Kl_s = (__nv_bfloat16*)(smraw + 55296);

    const int tid = threadIdx.x;
    const int warp = tid >> 5;
    const int lane = tid & 31;
    const int warp_m = warp & 3;
    const int warp_n = warp >> 2;
    const int bh = blockIdx.z;
    const int row0 = blockIdx.y * 128;
    const int col0 = blockIdx.x * 128;
    const long long hb = (long long)bh * SS * DH;

#pragma unroll
    for (int it = 0; it < 8; it++) {
        int v = tid + it * 256;
        int m = v >> 4;
        int kq = (v & 15) * 4;
        long long qi = hb + (long long)(row0 + m) * DH + kq;
        *(uint2*)&Qh_s[m * 72 + kq] = gldb4(g_qh, qi, QKV_ELEMS);
        *(uint2*)&Ql_s[m * 72 + kq] = gldb4(g_ql, qi, QKV_ELEMS);
        long long ki = hb + (long long)(col0 + m) * DH + kq;
        *(uint2*)&Kh_s[m * 72 + kq] = gldb4(g_kh, ki, QKV_ELEMS);
        *(uint2*)&Kl_s[m * 72 + kq] = gldb4(g_kl, ki, QKV_ELEMS);
    }
    __syncthreads();

    const int lr = lane >> 2;
    const int lc2 = (lane & 3) * 2;

    float acc[2][8][4];
#pragma unroll
    for (int a = 0; a < 2; a++)
#pragma unroll
        for (int b = 0; b < 8; b++)
#pragma unroll
            for (int c = 0; c < 4; c++) acc[a][b][c] = 0.f;

#pragma unroll
    for (int kc = 0; kc < 4; kc++) {
        int k0 = kc * 16;
        unsigned ah[2][4], al[2][4];
#pragma unroll
        for (int mt = 0; mt < 2; mt++) {
            int r = warp_m * 32 + mt * 16 + lr;
            ah[mt][0] = *(unsigned*)&Qh_s[r * 72 + k0 + lc2];
            ah[mt][1] = *(unsigned*)&Qh_s[(r + 8) * 72 + k0 + lc2];
            ah[mt][2] = *(unsigned*)&Qh_s[r * 72 + k0 + 8 + lc2];
            ah[mt][3] = *(unsigned*)&Qh_s[(r + 8) * 72 + k0 + 8 + lc2];
            al[mt][0] = *(unsigned*)&Ql_s[r * 72 + k0 + lc2];
            al[mt][1] = *(unsigned*)&Ql_s[(r + 8) * 72 + k0 + lc2];
            al[mt][2] = *(unsigned*)&Ql_s[r * 72 + k0 + 8 + lc2];
            al[mt][3] = *(unsigned*)&Ql_s[(r + 8) * 72 + k0 + 8 + lc2];
        }
#pragma unroll
        for (int nt = 0; nt < 8; nt++) {
            int c = warp_n * 64 + nt * 8 + lr;
            unsigned bh0 = *(unsigned*)&Kh_s[c * 72 + k0 + lc2];
            unsigned bh1 = *(unsigned*)&Kh_s[c * 72 + k0 + 8 + lc2];
            unsigned bl0 = *(unsigned*)&Kl_s[c * 72 + k0 + lc2];
            unsigned bl1 = *(unsigned*)&Kl_s[c * 72 + k0 + 8 + lc2];
#pragma unroll
            for (int mt = 0; mt < 2; mt++) {
                MMA_BF16(acc[mt][nt], ah[mt], bh0, bh1);
                MMA_BF16(acc[mt][nt], ah[mt], bl0, bl1);
                MMA_BF16(acc[mt][nt], al[mt], bh0, bh1);
            }
        }
    }

#pragma unroll
    for (int mt = 0; mt < 2; mt++) {
        int mrow = row0 + warp_m * 32 + mt * 16 + lr;
#pragma unroll
        for (int nt = 0; nt < 8; nt++) {
            int ncol = col0 + warp_n * 64 + nt * 8 + lc2;
            long long i0 = ((long long)bh * SS + mrow) * SS + ncol;
            long long i2 = ((long long)bh * SS + mrow + 8) * SS + ncol;
            gst2(attn, i0, ATTN_ELEMS, acc[mt][nt][0], acc[mt][nt][1]);
            gst2(attn, i2, ATTN_ELEMS, acc[mt][nt][2], acc[mt][nt][3]);
        }
    }
}

// ===========================================================================
// Row softmax over 2048 cols (unchanged).
// ===========================================================================
__global__ void __launch_bounds__(256) softmax_kernel(float* __restrict__ attn)
{
    __shared__ float red[8];
    const long long rbase = (long long)blockIdx.x * SS;
    const int tid = threadIdx.x;

    float4 v0 = gld4(attn, rbase + tid * 4, ATTN_ELEMS);
    float4 v1 = gld4(attn, rbase + 1024 + tid * 4, ATTN_ELEMS);

    float m = fmaxf(fmaxf(fmaxf(v0.x, v0.y), fmaxf(v0.z, v0.w)),
                    fmaxf(fmaxf(v1.x, v1.y), fmaxf(v1.z, v1.w)));
#pragma unroll
    for (int o = 16; o > 0; o >>= 1) m = fmaxf(m, __shfl_xor_sync(0xFFFFFFFFu, m, o));
    if ((tid & 31) == 0) red[tid >> 5] = m;
    __syncthreads();
    m = red[0];
#pragma unroll
    for (int w = 1; w < 8; w++) m = fmaxf(m, red[w]);
    __syncthreads();

    v0.x = __expf(v0.x - m); v0.y = __expf(v0.y - m);
    v0.z = __expf(v0.z - m); v0.w = __expf(v0.w - m);
    v1.x = __expf(v1.x - m); v1.y = __expf(v1.y - m);
    v1.z = __expf(v1.z - m); v1.w = __expf(v1.w - m);
    float s = v0.x + v0.y + v0.z + v0.w + v1.x + v1.y + v1.z + v1.w;
#pragma unroll
    for (int o = 16; o > 0; o >>= 1) s += __shfl_xor_sync(0xFFFFFFFFu, s, o);
    if ((tid & 31) == 0) red[tid >> 5] = s;
    __syncthreads();
    s = red[0];
#pragma unroll
    for (int w = 1; w < 8; w++) s += red[w];

    float inv = 1.f / s;
    v0.x *= inv; v0.y *= inv; v0.z *= inv; v0.w *= inv;
    v1.x *= inv; v1.y *= inv; v1.z *= inv; v1.w *= inv;

    long long i0 = rbase + tid * 4;
    long long i1 = rbase + 1024 + tid * 4;
    if (i0 + 3 < ATTN_ELEMS) *(float4*)(attn + i0) = v0;
    if (i1 + 3 < ATTN_ELEMS) *(float4*)(attn + i1) = v1;
}

// ===========================================================================
// AV via bf16x3 mma (unchanged; ctx emitted bf16 hi/lo).
// ===========================================================================
#define AV_SMEM 55296

__global__ void __launch_bounds__(256) av_mma_kernel(const float* __restrict__ attn)
{
    extern __shared__ __align__(16) char smraw[];
    __nv_bfloat16* Ph_s  = (__nv_bfloat16*)smraw;
    __nv_bfloat16* Pl_s  = (__nv_bfloat16*)(smraw + 18432);
    __nv_bfloat16* Vth_s = (__nv_bfloat16*)(smraw + 36864);
    __nv_bfloat16* Vtl_s = (__nv_bfloat16*)(smraw + 46080);

    const int tid = threadIdx.x;
    const int warp = tid >> 5;
    const int lane = tid & 31;
    const int warp_m = warp & 3;
    const int warp_n = warp >> 2;
    const int bh = blockIdx.y;
    const int row0 = blockIdx.x * 128;
    const long long pbase = (long long)bh * SS * SS;
    const long long vbase = (long long)bh * SS * DH;

    const int lr = lane >> 2;
    const int lc2 = (lane & 3) * 2;

    float acc[2][4][4];
#pragma unroll
    for (int a = 0; a < 2; a++)
#pragma unroll
        for (int b = 0; b < 4; b++)
#pragma unroll
            for (int c = 0; c < 4; c++) acc[a][b][c] = 0.f;

    for (int kk = 0; kk < SS; kk += 64) {
#pragma unroll
        for (int it = 0; it < 8; it++) {
            int v = tid + it * 256;
            int m = v >> 4;
            int kq = (v & 15) * 4;
            float4 p = gld4(attn, pbase + (long long)(row0 + m) * SS + kk + kq, ATTN_ELEMS);
            uint2 h, l;
            split4(p, h, l);
            *(uint2*)&Ph_s[m * 72 + kq] = h;
            *(uint2*)&Pl_s[m * 72 + kq] = l;
        }
#pragma unroll
        for (int it = 0; it < 4; it++) {
            int v = tid + it * 256;
            int k = v >> 4;
            int dq = (v & 15) * 4;
            float4 vv = gld4(g_v, vbase + (long long)(kk + k) * DH + dq, QKV_ELEMS);
            __nv_bfloat16 h, l;
            f2bf2(vv.x, h, l); Vth_s[(dq + 0) * 72 + k] = h; Vtl_s[(dq + 0) * 72 + k] = l;
            f2bf2(vv.y, h, l); Vth_s[(dq + 1) * 72 + k] = h; Vtl_s[(dq + 1) * 72 + k] = l;
            f2bf2(vv.z, h, l); Vth_s[(dq + 2) * 72 + k] = h; Vtl_s[(dq + 2) * 72 + k] = l;
            f2bf2(vv.w, h, l); Vth_s[(dq + 3) * 72 + k] = h; Vtl_s[(dq + 3) * 72 + k] = l;
        }
        __syncthreads();

#pragma unroll
        for (int kc = 0; kc < 4; kc++) {
            int k0 = kc * 16;
            unsigned ah[2][4], al[2][4];
#pragma unroll
            for (int mt = 0; mt < 2; mt++) {
                int r = warp_m * 32 + mt * 16 + lr;
                ah[mt][0] = *(unsigned*)&Ph_s[r * 72 + k0 + lc2];
                ah[mt][1] = *(unsigned*)&Ph_s[(r + 8) * 72 + k0 + lc2];
                ah[mt][2] = *(unsigned*)&Ph_s[r * 72 + k0 + 8 + lc2];
                ah[mt][3] = *(unsigned*)&Ph_s[(r + 8) * 72 + k0 + 8 + lc2];
                al[mt][0] = *(unsigned*)&Pl_s[r * 72 + k0 + lc2];
                al[mt][1] = *(unsigned*)&Pl_s[(r + 8) * 72 + k0 + lc2];
                al[mt][2] = *(unsigned*)&Pl_s[r * 72 + k0 + 8 + lc2];
                al[mt][3] = *(unsigned*)&Pl_s[(r + 8) * 72 + k0 + 8 + lc2];
            }
#pragma unroll
            for (int nt = 0; nt < 4; nt++) {
                int c = warp_n * 32 + nt * 8 + lr;
                unsigned bh0 = *(unsigned*)&Vth_s[c * 72 + k0 + lc2];
                unsigned bh1 = *(unsigned*)&Vth_s[c * 72 + k0 + 8 + lc2];
                unsigned bl0 = *(unsigned*)&Vtl_s[c * 72 + k0 + lc2];
                unsigned bl1 = *(unsigned*)&Vtl_s[c * 72 + k0 + 8 + lc2];
#pragma unroll
                for (int mt = 0; mt < 2; mt++) {
                    MMA_BF16(acc[mt][nt], ah[mt], bh0, bh1);
                    MMA_BF16(acc[mt][nt], ah[mt], bl0, bl1);
                    MMA_BF16(acc[mt][nt], al[mt], bh0, bh1);
                }
            }
        }
        __syncthreads();
    }

#pragma unroll
    for (int mt = 0; mt < 2; mt++) {
#pragma unroll
        for (int rr = 0; rr < 2; rr++) {
            int mrow = row0 + warp_m * 32 + mt * 16 + lr + rr * 8;
#pragma unroll
            for (int nt = 0; nt < 4; nt++) {
#pragma unroll
                for (int cc = 0; cc < 2; cc++) {
                    int dcol = warp_n * 32 + nt * 8 + lc2 + cc;
                    long long ci = vbase + (long long)mrow * DH + dcol;
                    __nv_bfloat16 h, l;
                    f2bf2(acc[mt][nt][rr * 2 + cc], h, l);
                    gstb(g_ctxh, ci, QKV_ELEMS, h);
                    gstb(g_ctxl, ci, QKV_ELEMS, l);
                }
            }
        }
    }
}

// ---------------------------------------------------------------------------
static bool s_capturing_probe()
{
    cudaStreamCaptureStatus st = cudaStreamCaptureStatusNone;
    cudaError_t e = cudaStreamIsCapturing(0, &st);
    if (e != cudaSuccess) { cudaGetLastError(); return true; }
    return st != cudaStreamCaptureStatusNone;
}

static void diag(const char* name, bool capturing)
{
    if (capturing) return;  // launches only during graph capture
    cudaError_t e = cudaDeviceSynchronize();
    fprintf(stderr, "[klaunch] %s: %s\n", name, cudaGetErrorString(e));
    cudaGetLastError();
}

extern "C" void kernel_launch(void* const* d_in, const int* in_sizes, int n_in,
                              void* d_out, int out_size)
{
    const float* query = (const float*)d_in[0];
    const float* key   = (const float*)d_in[1];
    const float* value = (const float*)d_in[2];
    const float* W_q   = (const float*)d_in[3];
    const float* b_q   = (const float*)d_in[4];
    const float* W_k   = (const float*)d_in[5];
    const float* b_k   = (const float*)d_in[6];
    const float* W_v   = (const float*)d_in[7];
    const float* b_v   = (const float*)d_in[8];
    const float* W_o   = (const float*)d_in[9];
    const float* b_o   = (const float*)d_in[10];

    float* out  = (float*)d_out;
    float* attn = out + OUT_ELEMS;  // confirmed: out_size == OUT_ELEMS + ATTN_ELEMS

    const bool capturing = s_capturing_probe();

    cudaFuncSetAttribute(scores_mma_kernel,
                         cudaFuncAttributeMaxDynamicSharedMemorySize, SCORES_SMEM);
    cudaFuncSetAttribute(av_mma_kernel,
                         cudaFuncAttributeMaxDynamicSharedMemorySize, AV_SMEM);

    dim3 gSplit(1024, 7);
    dim3 gProj(DM / 64, MM / 128);              // (12, 32)
    dim3 gOutProj(DM / 64, MM / 128);           // (12, 32)
    dim3 gScores(SS / 128, SS / 128, BB * HH);  // (16, 16, 24)
    dim3 gAV(SS / 128, BB * HH);                // (16, 24)

    split_all_kernel<<<gSplit, 256>>>(query, key, value, W_q, W_k, W_v, W_o);
    diag("split", capturing);

    proj_mma_kernel<0><<<gProj, 256>>>(b_q);
    diag("proj_q", capturing);
    proj_mma_kernel<1><<<gProj, 256>>>(b_k);
    diag("proj_k", capturing);
    proj_mma_kernel<2><<<gProj, 256>>>(b_v);
    diag("proj_v", capturing);

    scores_mma_kernel<<<gScores, 256, SCORES_SMEM>>>(attn);
    diag("scores_mma", capturing);

    softmax_kernel<<<BB * HH * SS, 256>>>(attn);
    diag("softmax", capturing);

    av_mma_kernel<<<gAV, 256, AV_SMEM>>>(attn);
    diag("av_mma", capturing);

    out_proj_mma_kernel<<<gOutProj, 256>>>(b_o, out);
    diag("out_proj", capturing);
}